// round 3
// baseline (speedup 1.0000x reference)
#include <cuda_runtime.h>
#include <cuda_bf16.h>
#include <cstdint>

#define T_TOK 8192
#define HDIM  2048
#define IDIM  4096
#define NEXP  8
#define TOPK  2

// ---------------- device scratch (static: no allocations allowed) ----------
__device__ int   g_cnt[NEXP];
__device__ int   g_off[NEXP];
__device__ int   g_tok[NEXP * T_TOK];
__device__ float g_wt [NEXP * T_TOK];
// act rows: exactly T_TOK*TOPK = 16384 rows of IDIM fp32 = 256 MB
__device__ float g_act[(size_t)T_TOK * TOPK * IDIM];

// ---------------- helpers --------------------------------------------------
__device__ __forceinline__ void mma16816(float* c, const uint32_t* a,
                                         uint32_t b0, uint32_t b1) {
    asm volatile(
        "mma.sync.aligned.m16n8k16.row.col.f32.bf16.bf16.f32 "
        "{%0,%1,%2,%3}, {%4,%5,%6,%7}, {%8,%9}, {%0,%1,%2,%3};\n"
        : "+f"(c[0]), "+f"(c[1]), "+f"(c[2]), "+f"(c[3])
        : "r"(a[0]), "r"(a[1]), "r"(a[2]), "r"(a[3]), "r"(b0), "r"(b1));
}

__device__ __forceinline__ uint32_t lds32(const __nv_bfloat16* p, int idx) {
    return *reinterpret_cast<const uint32_t*>(p + idx);
}

// split two fp32 into (hi,lo) bf16x2 pairs
__device__ __forceinline__ void split2(float a, float b,
                                       __nv_bfloat162& hi, __nv_bfloat162& lo) {
    __nv_bfloat16 ha = __float2bfloat16(a);
    __nv_bfloat16 hb = __float2bfloat16(b);
    hi = __halves2bfloat162(ha, hb);
    lo = __halves2bfloat162(__float2bfloat16(a - __bfloat162float(ha)),
                            __float2bfloat16(b - __bfloat162float(hb)));
}

__device__ __forceinline__ float silu(float x) {
    return x / (1.0f + __expf(-x));
}

// ---------------- kernel 1: zero output + counters --------------------------
__global__ void k_init(float* __restrict__ out) {
    size_t i = (size_t)blockIdx.x * blockDim.x + threadIdx.x;
    if (i < NEXP) g_cnt[i] = 0;
    const size_t n4 = (size_t)T_TOK * HDIM / 4;
    float4 z = make_float4(0.f, 0.f, 0.f, 0.f);
    for (size_t j = i; j < n4; j += (size_t)gridDim.x * blockDim.x)
        reinterpret_cast<float4*>(out)[j] = z;
}

// ---------------- kernel 2: router (top-2, normalized weights) --------------
__global__ void k_router(const float* __restrict__ logits) {
    int t = blockIdx.x * blockDim.x + threadIdx.x;
    if (t >= T_TOK) return;
    float l[NEXP];
#pragma unroll
    for (int i = 0; i < NEXP; i++) l[i] = logits[t * NEXP + i];

    float best = -3.402823e38f, sec = -3.402823e38f;
    int bi = 0, si = 0;
#pragma unroll
    for (int i = 0; i < NEXP; i++) {
        float v = l[i];
        if (v > best) { sec = best; si = bi; best = v; bi = i; }
        else if (v > sec) { sec = v; si = i; }
    }
    // normalized top-2 weights: softmax denominator cancels
    float wa = 1.0f / (1.0f + expf(sec - best));
    float wb = 1.0f - wa;

    int p = atomicAdd(&g_cnt[bi], 1);
    g_tok[bi * T_TOK + p] = t;  g_wt[bi * T_TOK + p] = wa;
    p = atomicAdd(&g_cnt[si], 1);
    g_tok[si * T_TOK + p] = t;  g_wt[si * T_TOK + p] = wb;
}

// ---------------- kernel 3: tiny exclusive scan over 8 counts ---------------
__global__ void k_offsets() {
    if (threadIdx.x == 0) {
        int s = 0;
        for (int e = 0; e < NEXP; e++) { g_off[e] = s; s += g_cnt[e]; }
    }
}

// ---------------- GEMM common constants -------------------------------------
// block: 256 threads = 8 warps (4 M x 2 N), block tile M=128
// smem stage: K-chunk of 32, bf16 hi/lo planes, padded stride 40 (bank-clean)
#define KC  32
#define STR 40

// ---------------- kernel 4: layer1  act = silu(x W13g^T) * (x W13u^T) -------
// grid: (M tiles = 64, act-col tiles of 64 = 64, experts = 8)
__global__ __launch_bounds__(256) void k_gemm1(const float* __restrict__ x,
                                               const float* __restrict__ w13) {
    __shared__ __nv_bfloat16 Ah[128 * STR], Al[128 * STR];
    __shared__ __nv_bfloat16 Bh[128 * STR], Bl[128 * STR];
    __shared__ int sTok[128];

    const int e = blockIdx.z;
    const int cnt_e = g_cnt[e];
    const int m0 = blockIdx.x * 128;
    if (m0 >= cnt_e) return;
    const int n0 = blockIdx.y * 64;            // act column base
    const int tid = threadIdx.x;

    if (tid < 128) {
        int r = m0 + tid;
        if (r >= cnt_e) r = cnt_e - 1;
        sTok[tid] = g_tok[e * T_TOK + r];
    }
    __syncthreads();

    const int warp = tid >> 5, lane = tid & 31;
    const int wm = warp & 3, wc = warp >> 2;
    const int g = lane >> 2, tg = lane & 3;

    float acc[2][8][4];
#pragma unroll
    for (int a = 0; a < 2; a++)
#pragma unroll
        for (int b = 0; b < 8; b++)
#pragma unroll
            for (int c = 0; c < 4; c++) acc[a][b][c] = 0.f;

    // staging: 2 threads per row, 16 fp32 each (4x float4)
    const int lrow = tid >> 1;
    const int lcol = (tid & 1) * 16;
    const float* w13e = w13 + (size_t)e * (2 * IDIM) * HDIM;
    const int j = lrow;
    const int wrow = (j < 64) ? (n0 + j) : (IDIM + n0 + (j - 64));
    const float* bptr = w13e + (size_t)wrow * HDIM + lcol;
    const float* aptr = x + (size_t)sTok[lrow] * HDIM + lcol;

    for (int kt = 0; kt < HDIM; kt += KC) {
#pragma unroll
        for (int q = 0; q < 4; q++) {
            float4 va = *reinterpret_cast<const float4*>(aptr + kt + q * 4);
            float4 vb = *reinterpret_cast<const float4*>(bptr + kt + q * 4);
            __nv_bfloat162 h0, l0, h1, l1;
            int base = lrow * STR + lcol + q * 4;
            split2(va.x, va.y, h0, l0); split2(va.z, va.w, h1, l1);
            reinterpret_cast<__nv_bfloat162*>(Ah + base)[0] = h0;
            reinterpret_cast<__nv_bfloat162*>(Ah + base)[1] = h1;
            reinterpret_cast<__nv_bfloat162*>(Al + base)[0] = l0;
            reinterpret_cast<__nv_bfloat162*>(Al + base)[1] = l1;
            split2(vb.x, vb.y, h0, l0); split2(vb.z, vb.w, h1, l1);
            reinterpret_cast<__nv_bfloat162*>(Bh + base)[0] = h0;
            reinterpret_cast<__nv_bfloat162*>(Bh + base)[1] = h1;
            reinterpret_cast<__nv_bfloat162*>(Bl + base)[0] = l0;
            reinterpret_cast<__nv_bfloat162*>(Bl + base)[1] = l1;
        }
        __syncthreads();

#pragma unroll
        for (int ks = 0; ks < 2; ks++) {
            const int kb = ks * 16;
            uint32_t ah[2][4], al[2][4];
#pragma unroll
            for (int mi = 0; mi < 2; mi++) {
                int row = wm * 32 + mi * 16 + g;
                int base = row * STR + kb + tg * 2;
                ah[mi][0] = lds32(Ah, base);
                ah[mi][1] = lds32(Ah, base + 8 * STR);
                ah[mi][2] = lds32(Ah, base + 8);
                ah[mi][3] = lds32(Ah, base + 8 * STR + 8);
                al[mi][0] = lds32(Al, base);
                al[mi][1] = lds32(Al, base + 8 * STR);
                al[mi][2] = lds32(Al, base + 8);
                al[mi][3] = lds32(Al, base + 8 * STR + 8);
            }
#pragma unroll
            for (int t = 0; t < 8; t++) {
                int j2 = (t < 4) ? (wc * 32 + t * 8 + g)
                                 : (64 + wc * 32 + (t - 4) * 8 + g);
                int bb = j2 * STR + kb + tg * 2;
                uint32_t bh0 = lds32(Bh, bb), bh1 = lds32(Bh, bb + 8);
                uint32_t bl0 = lds32(Bl, bb), bl1 = lds32(Bl, bb + 8);
#pragma unroll
                for (int mi = 0; mi < 2; mi++) {
                    mma16816(acc[mi][t], ah[mi], bh0, bh1);  // hi*hi
                    mma16816(acc[mi][t], ah[mi], bl0, bl1);  // hi*lo
                    mma16816(acc[mi][t], al[mi], bh0, bh1);  // lo*hi
                }
            }
        }
        __syncthreads();
    }

    // epilogue: silu(gate)*up, write act rows
    const int off_e = g_off[e];
#pragma unroll
    for (int mi = 0; mi < 2; mi++) {
#pragma unroll
        for (int t = 0; t < 4; t++) {
            int colb = n0 + wc * 32 + t * 8 + tg * 2;
            int rowl = wm * 32 + mi * 16 + g;
            int r0 = m0 + rowl, r1 = r0 + 8;
            if (r0 < cnt_e) {
                float2 v;
                v.x = silu(acc[mi][t][0]) * acc[mi][t + 4][0];
                v.y = silu(acc[mi][t][1]) * acc[mi][t + 4][1];
                *reinterpret_cast<float2*>(
                    &g_act[(size_t)(off_e + r0) * IDIM + colb]) = v;
            }
            if (r1 < cnt_e) {
                float2 v;
                v.x = silu(acc[mi][t][2]) * acc[mi][t + 4][2];
                v.y = silu(acc[mi][t][3]) * acc[mi][t + 4][3];
                *reinterpret_cast<float2*>(
                    &g_act[(size_t)(off_e + r1) * IDIM + colb]) = v;
            }
        }
    }
}

// ---------------- kernel 5: layer2  out += w * (act W2^T) -------------------
// grid: (M tiles = 64, N tiles = H/128 = 16, experts = 8)
__global__ __launch_bounds__(256) void k_gemm2(const float* __restrict__ w2,
                                               float* __restrict__ out) {
    __shared__ __nv_bfloat16 Ah[128 * STR], Al[128 * STR];
    __shared__ __nv_bfloat16 Bh[128 * STR], Bl[128 * STR];
    __shared__ int   sTok[128];
    __shared__ float sW[128];

    const int e = blockIdx.z;
    const int cnt_e = g_cnt[e];
    const int m0 = blockIdx.x * 128;
    if (m0 >= cnt_e) return;
    const int n0 = blockIdx.y * 128;
    const int tid = threadIdx.x;
    const int off_e = g_off[e];

    if (tid < 128) {
        int r = m0 + tid;
        if (r >= cnt_e) r = cnt_e - 1;
        sTok[tid] = g_tok[e * T_TOK + r];
        sW[tid]   = g_wt [e * T_TOK + r];
    }
    __syncthreads();

    const int warp = tid >> 5, lane = tid & 31;
    const int wm = warp & 3, wc = warp >> 2;
    const int g = lane >> 2, tg = lane & 3;

    float acc[2][8][4];
#pragma unroll
    for (int a = 0; a < 2; a++)
#pragma unroll
        for (int b = 0; b < 8; b++)
#pragma unroll
            for (int c = 0; c < 4; c++) acc[a][b][c] = 0.f;

    const int lrow = tid >> 1;
    const int lcol = (tid & 1) * 16;
    int rr = m0 + lrow;
    if (rr >= cnt_e) rr = cnt_e - 1;               // clamp: avoid OOB act reads
    const float* aptr = g_act + (size_t)(off_e + rr) * IDIM + lcol;
    const float* bptr = w2 + ((size_t)e * HDIM + (n0 + lrow)) * IDIM + lcol;

    for (int kt = 0; kt < IDIM; kt += KC) {
#pragma unroll
        for (int q = 0; q < 4; q++) {
            float4 va = *reinterpret_cast<const float4*>(aptr + kt + q * 4);
            float4 vb = *reinterpret_cast<const float4*>(bptr + kt + q * 4);
            __nv_bfloat162 h0, l0, h1, l1;
            int base = lrow * STR + lcol + q * 4;
            split2(va.x, va.y, h0, l0); split2(va.z, va.w, h1, l1);
            reinterpret_cast<__nv_bfloat162*>(Ah + base)[0] = h0;
            reinterpret_cast<__nv_bfloat162*>(Ah + base)[1] = h1;
            reinterpret_cast<__nv_bfloat162*>(Al + base)[0] = l0;
            reinterpret_cast<__nv_bfloat162*>(Al + base)[1] = l1;
            split2(vb.x, vb.y, h0, l0); split2(vb.z, vb.w, h1, l1);
            reinterpret_cast<__nv_bfloat162*>(Bh + base)[0] = h0;
            reinterpret_cast<__nv_bfloat162*>(Bh + base)[1] = h1;
            reinterpret_cast<__nv_bfloat162*>(Bl + base)[0] = l0;
            reinterpret_cast<__nv_bfloat162*>(Bl + base)[1] = l1;
        }
        __syncthreads();

#pragma unroll
        for (int ks = 0; ks < 2; ks++) {
            const int kb = ks * 16;
            uint32_t ah[2][4], al[2][4];
#pragma unroll
            for (int mi = 0; mi < 2; mi++) {
                int row = wm * 32 + mi * 16 + g;
                int base = row * STR + kb + tg * 2;
                ah[mi][0] = lds32(Ah, base);
                ah[mi][1] = lds32(Ah, base + 8 * STR);
                ah[mi][2] = lds32(Ah, base + 8);
                ah[mi][3] = lds32(Ah, base + 8 * STR + 8);
                al[mi][0] = lds32(Al, base);
                al[mi][1] = lds32(Al, base + 8 * STR);
                al[mi][2] = lds32(Al, base + 8);
                al[mi][3] = lds32(Al, base + 8 * STR + 8);
            }
#pragma unroll
            for (int t = 0; t < 8; t++) {
                int j2 = wc * 64 + t * 8 + g;
                int bb = j2 * STR + kb + tg * 2;
                uint32_t bh0 = lds32(Bh, bb), bh1 = lds32(Bh, bb + 8);
                uint32_t bl0 = lds32(Bl, bb), bl1 = lds32(Bl, bb + 8);
#pragma unroll
                for (int mi = 0; mi < 2; mi++) {
                    mma16816(acc[mi][t], ah[mi], bh0, bh1);
                    mma16816(acc[mi][t], ah[mi], bl0, bl1);
                    mma16816(acc[mi][t], al[mi], bh0, bh1);
                }
            }
        }
        __syncthreads();
    }

    // epilogue: weighted atomic accumulate into out[token]
#pragma unroll
    for (int mi = 0; mi < 2; mi++) {
#pragma unroll
        for (int t = 0; t < 8; t++) {
            int col = n0 + wc * 64 + t * 8 + tg * 2;
            int rowl = wm * 32 + mi * 16 + g;
            int r0 = m0 + rowl, r1 = r0 + 8;
            if (r0 < cnt_e) {
                float w = sW[rowl];
                size_t o = (size_t)sTok[rowl] * HDIM + col;
                atomicAdd(&out[o],     acc[mi][t][0] * w);
                atomicAdd(&out[o + 1], acc[mi][t][1] * w);
            }
            if (r1 < cnt_e) {
                float w = sW[rowl + 8];
                size_t o = (size_t)sTok[rowl + 8] * HDIM + col;
                atomicAdd(&out[o],     acc[mi][t][2] * w);
                atomicAdd(&out[o + 1], acc[mi][t][3] * w);
            }
        }
    }
}

// ---------------- launch ----------------------------------------------------
extern "C" void kernel_launch(void* const* d_in, const int* in_sizes, int n_in,
                              void* d_out, int out_size) {
    const float* x      = (const float*)d_in[0];   // [T, H]
    const float* logits = (const float*)d_in[1];   // [T, E]
    const float* w13    = (const float*)d_in[2];   // [E, 2I, H]
    const float* w2     = (const float*)d_in[3];   // [E, H, I]
    float* out = (float*)d_out;                    // [T, H]
    (void)in_sizes; (void)n_in; (void)out_size;

    k_init<<<2048, 256>>>(out);
    k_router<<<T_TOK / 256, 256>>>(logits);
    k_offsets<<<1, 32>>>();

    dim3 g1(T_TOK / 128, IDIM / 64, NEXP);
    k_gemm1<<<g1, 256>>>(x, w13);

    dim3 g2(T_TOK / 128, HDIM / 128, NEXP);
    k_gemm2<<<g2, 256>>>(w2, out);
}

// round 5
// speedup vs baseline: 1.6375x; 1.6375x over previous
#include <cuda_runtime.h>
#include <cuda_fp16.h>
#include <cstdint>

#define T_TOK 8192
#define HDIM  2048
#define IDIM  4096
#define NEXP  8
#define NSLOT (2 * T_TOK)

// ---------------- device scratch (static; no allocations allowed) -----------
__device__ int   g_cnt[NEXP];
__device__ int   g_off[NEXP];
__device__ int   g_tok[NEXP * T_TOK];
__device__ float g_wt [NEXP * T_TOK];
__device__ int   g_sl [2 * T_TOK];          // per token: (expert<<13)|pos, x2

__device__ __half g_xh [(size_t)T_TOK * HDIM];            // x hi plane
__device__ __half g_xl [(size_t)T_TOK * HDIM];            // x lo plane
__device__ __half g_w13[(size_t)NEXP * 2 * IDIM * HDIM];  // w13 fp16 (rounded)
__device__ __half g_w2 [(size_t)NEXP * HDIM * IDIM];      // w2  fp16 (rounded)
__device__ __half g_ah [(size_t)NSLOT * IDIM];            // act hi plane
__device__ __half g_al [(size_t)NSLOT * IDIM];            // act lo plane
__device__ float  g_y  [(size_t)NSLOT * HDIM];            // per-slot weighted y

// ---------------- helpers ----------------------------------------------------
__device__ __forceinline__ uint32_t smem_u32(const void* p) {
    uint32_t a;
    asm("{ .reg .u64 t; cvta.to.shared.u64 t, %1; cvt.u32.u64 %0, t; }"
        : "=r"(a) : "l"(p));
    return a;
}
#define CP16(d, s) \
    asm volatile("cp.async.cg.shared.global [%0], [%1], 16;" :: "r"(d), "l"(s) : "memory")
#define CPC()  asm volatile("cp.async.commit_group;" ::: "memory")
#define CPW1() asm volatile("cp.async.wait_group 1;" ::: "memory")

__device__ __forceinline__ void mma_h(float* c, const uint32_t* a,
                                      uint32_t b0, uint32_t b1) {
    asm volatile(
        "mma.sync.aligned.m16n8k16.row.col.f32.f16.f16.f32 "
        "{%0,%1,%2,%3}, {%4,%5,%6,%7}, {%8,%9}, {%0,%1,%2,%3};\n"
        : "+f"(c[0]), "+f"(c[1]), "+f"(c[2]), "+f"(c[3])
        : "r"(a[0]), "r"(a[1]), "r"(a[2]), "r"(a[3]), "r"(b0), "r"(b1));
}

__device__ __forceinline__ float silu(float x) { return x / (1.0f + __expf(-x)); }

__device__ __forceinline__ uint32_t h2u(__half2 h) {
    return *reinterpret_cast<uint32_t*>(&h);
}

// ---------------- tiny kernels ----------------------------------------------
__global__ void k_init() {
    if (threadIdx.x < NEXP) g_cnt[threadIdx.x] = 0;
}

__global__ void k_router(const float* __restrict__ logits) {
    int t = blockIdx.x * blockDim.x + threadIdx.x;
    if (t >= T_TOK) return;
    float l[NEXP];
#pragma unroll
    for (int i = 0; i < NEXP; i++) l[i] = logits[t * NEXP + i];
    float best = -3.402823e38f, sec = -3.402823e38f;
    int bi = 0, si = 0;
#pragma unroll
    for (int i = 0; i < NEXP; i++) {
        float v = l[i];
        if (v > best) { sec = best; si = bi; best = v; bi = i; }
        else if (v > sec) { sec = v; si = i; }
    }
    float wa = 1.0f / (1.0f + expf(sec - best));
    float wb = 1.0f - wa;
    int p = atomicAdd(&g_cnt[bi], 1);
    g_tok[bi * T_TOK + p] = t;  g_wt[bi * T_TOK + p] = wa;
    g_sl[2 * t] = (bi << 13) | p;
    p = atomicAdd(&g_cnt[si], 1);
    g_tok[si * T_TOK + p] = t;  g_wt[si * T_TOK + p] = wb;
    g_sl[2 * t + 1] = (si << 13) | p;
}

__global__ void k_offsets() {
    if (threadIdx.x == 0) {
        int s = 0;
        for (int e = 0; e < NEXP; e++) { g_off[e] = s; s += g_cnt[e]; }
    }
}

// ---------------- prep: fp32 -> fp16 planes ----------------------------------
__device__ __forceinline__ void split_store(const float* in, __half* hi, __half* lo,
                                            size_t n4) {
    size_t i = (size_t)blockIdx.x * blockDim.x + threadIdx.x;
    for (; i < n4; i += (size_t)gridDim.x * blockDim.x) {
        float4 v = reinterpret_cast<const float4*>(in)[i];
        __half h0 = __float2half_rn(v.x), h1 = __float2half_rn(v.y);
        __half h2 = __float2half_rn(v.z), h3 = __float2half_rn(v.w);
        __half l0 = __float2half_rn(v.x - __half2float(h0));
        __half l1 = __float2half_rn(v.y - __half2float(h1));
        __half l2 = __float2half_rn(v.z - __half2float(h2));
        __half l3 = __float2half_rn(v.w - __half2float(h3));
        uint2 uh = make_uint2(h2u(__halves2half2(h0, h1)), h2u(__halves2half2(h2, h3)));
        uint2 ul = make_uint2(h2u(__halves2half2(l0, l1)), h2u(__halves2half2(l2, l3)));
        reinterpret_cast<uint2*>(hi)[i] = uh;
        reinterpret_cast<uint2*>(lo)[i] = ul;
    }
}
__device__ __forceinline__ void round_store(const float* in, __half* hi, size_t n4) {
    size_t i = (size_t)blockIdx.x * blockDim.x + threadIdx.x;
    for (; i < n4; i += (size_t)gridDim.x * blockDim.x) {
        float4 v = reinterpret_cast<const float4*>(in)[i];
        uint2 u = make_uint2(
            h2u(__halves2half2(__float2half_rn(v.x), __float2half_rn(v.y))),
            h2u(__halves2half2(__float2half_rn(v.z), __float2half_rn(v.w))));
        reinterpret_cast<uint2*>(hi)[i] = u;
    }
}
__global__ void k_prep_x(const float* __restrict__ in) {
    split_store(in, g_xh, g_xl, (size_t)T_TOK * HDIM / 4);
}
__global__ void k_prep_w13(const float* __restrict__ in) {
    round_store(in, g_w13, (size_t)NEXP * 2 * IDIM * HDIM / 4);
}
__global__ void k_prep_w2(const float* __restrict__ in) {
    round_store(in, g_w2, (size_t)NEXP * HDIM * IDIM / 4);
}

// ---------------- GEMM config ------------------------------------------------
// block 128M x 256N(smem rows), 8 warps, warp tile 64x64, KC=32, 3-stage cp.async
#define KC     32
#define SROWB  80                       // 40 halves, 16B-aligned stride
#define APL    (128 * SROWB)            // A plane 10240B
#define STG_   (2 * APL + 256 * SROWB)  // 40960B per stage
#define NSTG   3
#define SM_TOK 0
#define SM_WT  512
#define SM_BUF 1024
#define SMEM_SZ (SM_BUF + NSTG * STG_)  // ~124 KB

// ---------------- gemm1: act = silu(x W13g^T) * (x W13u^T) -------------------
// grid (T/128, IDIM/128, E); smem B rows: per warp 32 gate + 32 up cols
__global__ __launch_bounds__(256) void k_gemm1(const int dummy) {
    extern __shared__ char dsm[];
    const int e = blockIdx.z;
    const int cnt = g_cnt[e];
    const int m0 = blockIdx.x * 128;
    if (m0 >= cnt) return;
    const int n0 = blockIdx.y * 128;
    const int tid = threadIdx.x, wid = tid >> 5, lane = tid & 31;
    int* sTok = (int*)(dsm + SM_TOK);
    if (tid < 128) {
        int r = m0 + tid; if (r >= cnt) r = cnt - 1;
        sTok[tid] = g_tok[e * T_TOK + r];
    }
    __syncthreads();
    const uint32_t sb = smem_u32(dsm);

    // staging assignment
    const int arow = tid >> 1, ahalf = tid & 1;
    const __half* asrcH = g_xh + (size_t)sTok[arow] * HDIM + ahalf * 16;
    const __half* asrcL = g_xl + (size_t)sTok[arow] * HDIM + ahalf * 16;
    const uint32_t adst = sb + SM_BUF + arow * SROWB + ahalf * 32;
    const int brow = tid, wnb = brow >> 6, idx = brow & 63;
    const int wrow = (idx < 32) ? (n0 + wnb * 32 + idx)
                                : (IDIM + n0 + wnb * 32 + (idx - 32));
    const __half* bsrc = g_w13 + ((size_t)e * 2 * IDIM + wrow) * HDIM;
    const uint32_t bdst = sb + SM_BUF + 2 * APL + brow * SROWB;

    const int wm = wid & 1, wn = wid >> 1, g = lane >> 2, tg = lane & 3;
    float acc[4][8][4];
#pragma unroll
    for (int a = 0; a < 4; a++)
#pragma unroll
        for (int b = 0; b < 8; b++)
#pragma unroll
            for (int c = 0; c < 4; c++) acc[a][b][c] = 0.f;

#define G1_ISSUE(c, s) do {                                    \
        uint32_t so = (s) * STG_;                              \
        const __half* pa = asrcH + (c) * KC;                   \
        CP16(adst + so,            pa);                        \
        CP16(adst + so + 16,       pa + 8);                    \
        const __half* pl = asrcL + (c) * KC;                   \
        CP16(adst + so + APL,      pl);                        \
        CP16(adst + so + APL + 16, pl + 8);                    \
        const __half* pb = bsrc + (c) * KC;                    \
        CP16(bdst + so,      pb);      CP16(bdst + so + 16, pb + 8);  \
        CP16(bdst + so + 32, pb + 16); CP16(bdst + so + 48, pb + 24); \
    } while (0)

    G1_ISSUE(0, 0); CPC();
    G1_ISSUE(1, 1); CPC();

    const int NCH = HDIM / KC;   // 64
    for (int c = 0; c < NCH; c++) {
        CPW1();
        __syncthreads();
        const char* st = dsm + SM_BUF + (c % NSTG) * STG_;
        const char* Ah = st;
        const char* Al = st + APL;
        const char* Bp = st + 2 * APL;
#pragma unroll
        for (int ks = 0; ks < 2; ks++) {
            uint32_t ah[4][4], al[4][4];
#pragma unroll
            for (int mf = 0; mf < 4; mf++) {
                const char* p = Ah + (wm * 64 + mf * 16 + g) * SROWB + ks * 32 + tg * 4;
                ah[mf][0] = *(const uint32_t*)p;
                ah[mf][1] = *(const uint32_t*)(p + 8 * SROWB);
                ah[mf][2] = *(const uint32_t*)(p + 16);
                ah[mf][3] = *(const uint32_t*)(p + 8 * SROWB + 16);
                const char* q = Al + (wm * 64 + mf * 16 + g) * SROWB + ks * 32 + tg * 4;
                al[mf][0] = *(const uint32_t*)q;
                al[mf][1] = *(const uint32_t*)(q + 8 * SROWB);
                al[mf][2] = *(const uint32_t*)(q + 16);
                al[mf][3] = *(const uint32_t*)(q + 8 * SROWB + 16);
            }
#pragma unroll
            for (int nf = 0; nf < 8; nf++) {
                const char* p = Bp + (wn * 64 + nf * 8 + g) * SROWB + ks * 32 + tg * 4;
                uint32_t b0 = *(const uint32_t*)p;
                uint32_t b1 = *(const uint32_t*)(p + 16);
#pragma unroll
                for (int mf = 0; mf < 4; mf++) {
                    mma_h(acc[mf][nf], ah[mf], b0, b1);   // a_hi * b
                    mma_h(acc[mf][nf], al[mf], b0, b1);   // a_lo * b
                }
            }
        }
        if (c + 2 < NCH) G1_ISSUE(c + 2, (c + 2) % NSTG);
        CPC();
    }
#undef G1_ISSUE

    // epilogue: silu(gate)*up -> act fp16 hi/lo planes
    const int off_e = g_off[e];
#pragma unroll
    for (int mf = 0; mf < 4; mf++) {
#pragma unroll
        for (int nf = 0; nf < 4; nf++) {
            int col = n0 + wn * 32 + nf * 8 + tg * 2;
#pragma unroll
            for (int h = 0; h < 2; h++) {
                int rl = wm * 64 + mf * 16 + g + h * 8;
                int r = m0 + rl;
                if (r < cnt) {
                    float a0 = silu(acc[mf][nf][2 * h])     * acc[mf][nf + 4][2 * h];
                    float a1 = silu(acc[mf][nf][2 * h + 1]) * acc[mf][nf + 4][2 * h + 1];
                    __half h0 = __float2half_rn(a0), h1 = __float2half_rn(a1);
                    __half l0 = __float2half_rn(a0 - __half2float(h0));
                    __half l1 = __float2half_rn(a1 - __half2float(h1));
                    size_t o = (size_t)(off_e + r) * IDIM + col;
                    *reinterpret_cast<__half2*>(g_ah + o) = __halves2half2(h0, h1);
                    *reinterpret_cast<__half2*>(g_al + o) = __halves2half2(l0, l1);
                }
            }
        }
    }
    (void)dummy;
}

// ---------------- gemm2: y[slot] = w * (act W2^T) ----------------------------
// grid (T/128, HDIM/256, E)
__global__ __launch_bounds__(256) void k_gemm2(const int dummy) {
    extern __shared__ char dsm[];
    const int e = blockIdx.z;
    const int cnt = g_cnt[e];
    const int m0 = blockIdx.x * 128;
    if (m0 >= cnt) return;
    const int n0 = blockIdx.y * 256;
    const int tid = threadIdx.x, wid = tid >> 5, lane = tid & 31;
    const int off_e = g_off[e];
    float* sW = (float*)(dsm + SM_WT);
    if (tid < 128) {
        int r = m0 + tid; if (r >= cnt) r = cnt - 1;
        sW[tid] = g_wt[e * T_TOK + r];
    }
    __syncthreads();
    const uint32_t sb = smem_u32(dsm);

    const int arow = tid >> 1, ahalf = tid & 1;
    int rr = m0 + arow; if (rr >= cnt) rr = cnt - 1;
    const __half* asrcH = g_ah + (size_t)(off_e + rr) * IDIM + ahalf * 16;
    const __half* asrcL = g_al + (size_t)(off_e + rr) * IDIM + ahalf * 16;
    const uint32_t adst = sb + SM_BUF + arow * SROWB + ahalf * 32;
    const __half* bsrc = g_w2 + ((size_t)e * HDIM + (n0 + tid)) * IDIM;
    const uint32_t bdst = sb + SM_BUF + 2 * APL + tid * SROWB;

    const int wm = wid & 1, wn = wid >> 1, g = lane >> 2, tg = lane & 3;
    float acc[4][8][4];
#pragma unroll
    for (int a = 0; a < 4; a++)
#pragma unroll
        for (int b = 0; b < 8; b++)
#pragma unroll
            for (int c = 0; c < 4; c++) acc[a][b][c] = 0.f;

#define G2_ISSUE(c, s) do {                                    \
        uint32_t so = (s) * STG_;                              \
        const __half* pa = asrcH + (c) * KC;                   \
        CP16(adst + so,            pa);                        \
        CP16(adst + so + 16,       pa + 8);                    \
        const __half* pl = asrcL + (c) * KC;                   \
        CP16(adst + so + APL,      pl);                        \
        CP16(adst + so + APL + 16, pl + 8);                    \
        const __half* pb = bsrc + (c) * KC;                    \
        CP16(bdst + so,      pb);      CP16(bdst + so + 16, pb + 8);  \
        CP16(bdst + so + 32, pb + 16); CP16(bdst + so + 48, pb + 24); \
    } while (0)

    G2_ISSUE(0, 0); CPC();
    G2_ISSUE(1, 1); CPC();

    const int NCH = IDIM / KC;   // 128
    for (int c = 0; c < NCH; c++) {
        CPW1();
        __syncthreads();
        const char* st = dsm + SM_BUF + (c % NSTG) * STG_;
        const char* Ah = st;
        const char* Al = st + APL;
        const char* Bp = st + 2 * APL;
#pragma unroll
        for (int ks = 0; ks < 2; ks++) {
            uint32_t ah[4][4], al[4][4];
#pragma unroll
            for (int mf = 0; mf < 4; mf++) {
                const char* p = Ah + (wm * 64 + mf * 16 + g) * SROWB + ks * 32 + tg * 4;
                ah[mf][0] = *(const uint32_t*)p;
                ah[mf][1] = *(const uint32_t*)(p + 8 * SROWB);
                ah[mf][2] = *(const uint32_t*)(p + 16);
                ah[mf][3] = *(const uint32_t*)(p + 8 * SROWB + 16);
                const char* q = Al + (wm * 64 + mf * 16 + g) * SROWB + ks * 32 + tg * 4;
                al[mf][0] = *(const uint32_t*)q;
                al[mf][1] = *(const uint32_t*)(q + 8 * SROWB);
                al[mf][2] = *(const uint32_t*)(q + 16);
                al[mf][3] = *(const uint32_t*)(q + 8 * SROWB + 16);
            }
#pragma unroll
            for (int nf = 0; nf < 8; nf++) {
                const char* p = Bp + (wn * 64 + nf * 8 + g) * SROWB + ks * 32 + tg * 4;
                uint32_t b0 = *(const uint32_t*)p;
                uint32_t b1 = *(const uint32_t*)(p + 16);
#pragma unroll
                for (int mf = 0; mf < 4; mf++) {
                    mma_h(acc[mf][nf], ah[mf], b0, b1);
                    mma_h(acc[mf][nf], al[mf], b0, b1);
                }
            }
        }
        if (c + 2 < NCH) G2_ISSUE(c + 2, (c + 2) % NSTG);
        CPC();
    }
#undef G2_ISSUE

    // epilogue: weighted store to per-slot y buffer (no atomics)
#pragma unroll
    for (int mf = 0; mf < 4; mf++) {
#pragma unroll
        for (int nf = 0; nf < 8; nf++) {
            int col = n0 + wn * 64 + nf * 8 + tg * 2;
#pragma unroll
            for (int h = 0; h < 2; h++) {
                int rl = wm * 64 + mf * 16 + g + h * 8;
                int r = m0 + rl;
                if (r < cnt) {
                    float w = sW[rl];
                    size_t o = (size_t)(off_e + r) * HDIM + col;
                    *reinterpret_cast<float2*>(g_y + o) =
                        make_float2(acc[mf][nf][2 * h] * w, acc[mf][nf][2 * h + 1] * w);
                }
            }
        }
    }
    (void)dummy;
}

// ---------------- combine: out[t] = y[slot0] + y[slot1] ----------------------
__global__ void k_combine(float* __restrict__ out) {
    const size_t n4 = (size_t)T_TOK * HDIM / 4;
    size_t i = (size_t)blockIdx.x * blockDim.x + threadIdx.x;
    for (; i < n4; i += (size_t)gridDim.x * blockDim.x) {
        int t = (int)(i / (HDIM / 4));
        int c = (int)(i % (HDIM / 4));
        int p0 = g_sl[2 * t], p1 = g_sl[2 * t + 1];
        size_t s0 = (size_t)g_off[p0 >> 13] + (p0 & 8191);
        size_t s1 = (size_t)g_off[p1 >> 13] + (p1 & 8191);
        float4 a = reinterpret_cast<const float4*>(g_y)[s0 * (HDIM / 4) + c];
        float4 b = reinterpret_cast<const float4*>(g_y)[s1 * (HDIM / 4) + c];
        reinterpret_cast<float4*>(out)[i] =
            make_float4(a.x + b.x, a.y + b.y, a.z + b.z, a.w + b.w);
    }
}

// ---------------- launch ------------------------------------------------------
extern "C" void kernel_launch(void* const* d_in, const int* in_sizes, int n_in,
                              void* d_out, int out_size) {
    const float* x      = (const float*)d_in[0];   // [T, H]
    const float* logits = (const float*)d_in[1];   // [T, E]
    const float* w13    = (const float*)d_in[2];   // [E, 2I, H]
    const float* w2     = (const float*)d_in[3];   // [E, H, I]
    float* out = (float*)d_out;                    // [T, H]
    (void)in_sizes; (void)n_in; (void)out_size;

    cudaFuncSetAttribute(k_gemm1, cudaFuncAttributeMaxDynamicSharedMemorySize, SMEM_SZ);
    cudaFuncSetAttribute(k_gemm2, cudaFuncAttributeMaxDynamicSharedMemorySize, SMEM_SZ);

    k_init<<<1, 32>>>();
    k_router<<<T_TOK / 256, 256>>>(logits);
    k_offsets<<<1, 32>>>();
    k_prep_x  <<<2048, 256>>>(x);
    k_prep_w13<<<8192, 256>>>(w13);
    k_prep_w2 <<<4096, 256>>>(w2);

    dim3 g1(T_TOK / 128, IDIM / 128, NEXP);
    k_gemm1<<<g1, 256, SMEM_SZ>>>(0);

    dim3 g2(T_TOK / 128, HDIM / 256, NEXP);
    k_gemm2<<<g2, 256, SMEM_SZ>>>(0);

    k_combine<<<2048, 256>>>(out);
}

// round 7
// speedup vs baseline: 2.3159x; 1.4143x over previous
#include <cuda_runtime.h>
#include <cuda_fp16.h>
#include <cstdint>

#define T_TOK 8192
#define HDIM  2048
#define IDIM  4096
#define NEXP  8
#define NSLOT (2 * T_TOK)

// ---------------- device scratch (static; no allocations allowed) -----------
__device__ int   g_cnt[NEXP];
__device__ int   g_off[NEXP];
__device__ int   g_tok[NEXP * T_TOK];
__device__ float g_wt [NEXP * T_TOK];
__device__ int   g_sl [2 * T_TOK];          // per token: (expert<<13)|pos, x2

__device__ __half g_x  [(size_t)T_TOK * HDIM];            // x fp16
__device__ __half g_w13[(size_t)NEXP * 2 * IDIM * HDIM];  // w13 fp16
__device__ __half g_w2 [(size_t)NEXP * HDIM * IDIM];      // w2  fp16
__device__ __half g_a  [(size_t)NSLOT * IDIM];            // act fp16
__device__ float  g_y  [(size_t)NSLOT * HDIM];            // per-slot weighted y

// ---------------- helpers ----------------------------------------------------
__device__ __forceinline__ uint32_t smem_u32(const void* p) {
    uint32_t a;
    asm("{ .reg .u64 t; cvta.to.shared.u64 t, %1; cvt.u32.u64 %0, t; }"
        : "=r"(a) : "l"(p));
    return a;
}
#define CP16(d, s) \
    asm volatile("cp.async.cg.shared.global [%0], [%1], 16;" :: "r"(d), "l"(s) : "memory")
#define CPC()  asm volatile("cp.async.commit_group;" ::: "memory")
#define CPW()  asm volatile("cp.async.wait_group 1;" ::: "memory")

__device__ __forceinline__ void mma_h(float* c, const uint32_t* a,
                                      uint32_t b0, uint32_t b1) {
    asm volatile(
        "mma.sync.aligned.m16n8k16.row.col.f32.f16.f16.f32 "
        "{%0,%1,%2,%3}, {%4,%5,%6,%7}, {%8,%9}, {%0,%1,%2,%3};\n"
        : "+f"(c[0]), "+f"(c[1]), "+f"(c[2]), "+f"(c[3])
        : "r"(a[0]), "r"(a[1]), "r"(a[2]), "r"(a[3]), "r"(b0), "r"(b1));
}

__device__ __forceinline__ float silu(float x) { return x / (1.0f + __expf(-x)); }

__device__ __forceinline__ uint32_t h2u(__half2 h) {
    return *reinterpret_cast<uint32_t*>(&h);
}

// ---------------- tiny kernels ----------------------------------------------
__global__ void k_init() {
    if (threadIdx.x < NEXP) g_cnt[threadIdx.x] = 0;
}

__global__ void k_router(const float* __restrict__ logits) {
    int t = blockIdx.x * blockDim.x + threadIdx.x;
    if (t >= T_TOK) return;
    float l[NEXP];
#pragma unroll
    for (int i = 0; i < NEXP; i++) l[i] = logits[t * NEXP + i];
    float best = -3.402823e38f, sec = -3.402823e38f;
    int bi = 0, si = 0;
#pragma unroll
    for (int i = 0; i < NEXP; i++) {
        float v = l[i];
        if (v > best) { sec = best; si = bi; best = v; bi = i; }
        else if (v > sec) { sec = v; si = i; }
    }
    float wa = 1.0f / (1.0f + expf(sec - best));
    float wb = 1.0f - wa;
    int p = atomicAdd(&g_cnt[bi], 1);
    g_tok[bi * T_TOK + p] = t;  g_wt[bi * T_TOK + p] = wa;
    g_sl[2 * t] = (bi << 13) | p;
    p = atomicAdd(&g_cnt[si], 1);
    g_tok[si * T_TOK + p] = t;  g_wt[si * T_TOK + p] = wb;
    g_sl[2 * t + 1] = (si << 13) | p;
}

__global__ void k_offsets() {
    if (threadIdx.x == 0) {
        int s = 0;
        for (int e = 0; e < NEXP; e++) { g_off[e] = s; s += g_cnt[e]; }
    }
}

// ---------------- prep: fp32 -> fp16 (round-to-nearest) ----------------------
__device__ __forceinline__ void round_store(const float* in, __half* hi, size_t n4) {
    size_t i = (size_t)blockIdx.x * blockDim.x + threadIdx.x;
    for (; i < n4; i += (size_t)gridDim.x * blockDim.x) {
        float4 v = reinterpret_cast<const float4*>(in)[i];
        uint2 u = make_uint2(
            h2u(__halves2half2(__float2half_rn(v.x), __float2half_rn(v.y))),
            h2u(__halves2half2(__float2half_rn(v.z), __float2half_rn(v.w))));
        reinterpret_cast<uint2*>(hi)[i] = u;
    }
}
__global__ void k_prep_x(const float* __restrict__ in) {
    round_store(in, g_x, (size_t)T_TOK * HDIM / 4);
}
__global__ void k_prep_w13(const float* __restrict__ in) {
    round_store(in, g_w13, (size_t)NEXP * 2 * IDIM * HDIM / 4);
}
__global__ void k_prep_w2(const float* __restrict__ in) {
    round_store(in, g_w2, (size_t)NEXP * HDIM * IDIM / 4);
}

// ---------------- GEMM config ------------------------------------------------
// block 128M x 256N smem rows, 8 warps (2M x 4N), warp tile 64x64
// KC=64 halves per chunk, 3-stage cp.async pipeline
#define KC     64
#define SROWB  144                      // 64 halves (128B) + 16B pad
#define APL    (128 * SROWB)            // A plane 18432B
#define STG_   (APL + 256 * SROWB)      // 55296B per stage
#define NSTG   3
#define SM_TOK 0
#define SM_WT  512
#define SM_BUF 1024
#define SMEM_SZ (SM_BUF + NSTG * STG_)  // ~164 KB

// ---------------- gemm1: act = silu(x W13g^T) * (x W13u^T) -------------------
// grid (T/128, IDIM/128, E)
__global__ __launch_bounds__(256) void k_gemm1(const int dummy) {
    extern __shared__ char dsm[];
    const int e = blockIdx.z;
    const int cnt = g_cnt[e];
    const int m0 = blockIdx.x * 128;
    if (m0 >= cnt) return;
    const int n0 = blockIdx.y * 128;
    const int tid = threadIdx.x, wid = tid >> 5, lane = tid & 31;
    int* sTok = (int*)(dsm + SM_TOK);
    if (tid < 128) {
        int r = m0 + tid; if (r >= cnt) r = cnt - 1;
        sTok[tid] = g_tok[e * T_TOK + r];
    }
    __syncthreads();
    const uint32_t sb = smem_u32(dsm);

    // staging: A 2 threads/row x 64B each; B 1 thread/row x 128B
    const int arow = tid >> 1, ahalf = tid & 1;
    const __half* asrc = g_x + (size_t)sTok[arow] * HDIM + ahalf * 32;
    const uint32_t adst = sb + SM_BUF + arow * SROWB + ahalf * 64;
    const int brow = tid, wnb = brow >> 6, idx = brow & 63;
    const int wrow = (idx < 32) ? (n0 + wnb * 32 + idx)
                                : (IDIM + n0 + wnb * 32 + (idx - 32));
    const __half* bsrc = g_w13 + ((size_t)e * 2 * IDIM + wrow) * HDIM;
    const uint32_t bdst = sb + SM_BUF + APL + brow * SROWB;

    const int wm = wid & 1, wn = wid >> 1, g = lane >> 2, tg = lane & 3;
    float acc[4][8][4];
#pragma unroll
    for (int a = 0; a < 4; a++)
#pragma unroll
        for (int b = 0; b < 8; b++)
#pragma unroll
            for (int c = 0; c < 4; c++) acc[a][b][c] = 0.f;

#define G1_ISSUE(c, s) do {                                           \
        uint32_t so = (s) * STG_;                                     \
        const __half* pa = asrc + (c) * KC;                           \
        CP16(adst + so,      pa);      CP16(adst + so + 16, pa + 8);  \
        CP16(adst + so + 32, pa + 16); CP16(adst + so + 48, pa + 24); \
        const __half* pb = bsrc + (c) * KC;                           \
        CP16(bdst + so,      pb);      CP16(bdst + so + 16, pb + 8);  \
        CP16(bdst + so + 32, pb + 16); CP16(bdst + so + 48, pb + 24); \
        CP16(bdst + so + 64, pb + 32); CP16(bdst + so + 80, pb + 40); \
        CP16(bdst + so + 96, pb + 48); CP16(bdst + so + 112, pb + 56);\
    } while (0)

    G1_ISSUE(0, 0); CPC();
    G1_ISSUE(1, 1); CPC();

    const int NCH = HDIM / KC;   // 32
    for (int c = 0; c < NCH; c++) {
        CPW();
        __syncthreads();
        const char* st = dsm + SM_BUF + (c % NSTG) * STG_;
        const char* Ap = st;
        const char* Bp = st + APL;
#pragma unroll
        for (int ks = 0; ks < 4; ks++) {
            uint32_t af[4][4];
#pragma unroll
            for (int mf = 0; mf < 4; mf++) {
                const char* p = Ap + (wm * 64 + mf * 16 + g) * SROWB + ks * 32 + tg * 4;
                af[mf][0] = *(const uint32_t*)p;
                af[mf][1] = *(const uint32_t*)(p + 8 * SROWB);
                af[mf][2] = *(const uint32_t*)(p + 16);
                af[mf][3] = *(const uint32_t*)(p + 8 * SROWB + 16);
            }
#pragma unroll
            for (int nf = 0; nf < 8; nf++) {
                const char* p = Bp + (wn * 64 + nf * 8 + g) * SROWB + ks * 32 + tg * 4;
                uint32_t b0 = *(const uint32_t*)p;
                uint32_t b1 = *(const uint32_t*)(p + 16);
#pragma unroll
                for (int mf = 0; mf < 4; mf++)
                    mma_h(acc[mf][nf], af[mf], b0, b1);
            }
        }
        if (c + 2 < NCH) G1_ISSUE(c + 2, (c + 2) % NSTG);
        CPC();
    }
#undef G1_ISSUE

    // epilogue: silu(gate)*up -> act fp16
    const int off_e = g_off[e];
#pragma unroll
    for (int mf = 0; mf < 4; mf++) {
#pragma unroll
        for (int nf = 0; nf < 4; nf++) {
            int col = n0 + wn * 32 + nf * 8 + tg * 2;
#pragma unroll
            for (int h = 0; h < 2; h++) {
                int rl = wm * 64 + mf * 16 + g + h * 8;
                int r = m0 + rl;
                if (r < cnt) {
                    float a0 = silu(acc[mf][nf][2 * h])     * acc[mf][nf + 4][2 * h];
                    float a1 = silu(acc[mf][nf][2 * h + 1]) * acc[mf][nf + 4][2 * h + 1];
                    size_t o = (size_t)(off_e + r) * IDIM + col;
                    *reinterpret_cast<__half2*>(g_a + o) =
                        __halves2half2(__float2half_rn(a0), __float2half_rn(a1));
                }
            }
        }
    }
    (void)dummy;
}

// ---------------- gemm2: y[slot] = w * (act W2^T) ----------------------------
// grid (T/128, HDIM/256, E)
__global__ __launch_bounds__(256) void k_gemm2(const int dummy) {
    extern __shared__ char dsm[];
    const int e = blockIdx.z;
    const int cnt = g_cnt[e];
    const int m0 = blockIdx.x * 128;
    if (m0 >= cnt) return;
    const int n0 = blockIdx.y * 256;
    const int tid = threadIdx.x, wid = tid >> 5, lane = tid & 31;
    const int off_e = g_off[e];
    float* sW = (float*)(dsm + SM_WT);
    if (tid < 128) {
        int r = m0 + tid; if (r >= cnt) r = cnt - 1;
        sW[tid] = g_wt[e * T_TOK + r];
    }
    __syncthreads();
    const uint32_t sb = smem_u32(dsm);

    const int arow = tid >> 1, ahalf = tid & 1;
    int rr = m0 + arow; if (rr >= cnt) rr = cnt - 1;
    const __half* asrc = g_a + (size_t)(off_e + rr) * IDIM + ahalf * 32;
    const uint32_t adst = sb + SM_BUF + arow * SROWB + ahalf * 64;
    const __half* bsrc = g_w2 + ((size_t)e * HDIM + (n0 + tid)) * IDIM;
    const uint32_t bdst = sb + SM_BUF + APL + tid * SROWB;

    const int wm = wid & 1, wn = wid >> 1, g = lane >> 2, tg = lane & 3;
    float acc[4][8][4];
#pragma unroll
    for (int a = 0; a < 4; a++)
#pragma unroll
        for (int b = 0; b < 8; b++)
#pragma unroll
            for (int c = 0; c < 4; c++) acc[a][b][c] = 0.f;

#define G2_ISSUE(c, s) do {                                           \
        uint32_t so = (s) * STG_;                                     \
        const __half* pa = asrc + (c) * KC;                           \
        CP16(adst + so,      pa);      CP16(adst + so + 16, pa + 8);  \
        CP16(adst + so + 32, pa + 16); CP16(adst + so + 48, pa + 24); \
        const __half* pb = bsrc + (c) * KC;                           \
        CP16(bdst + so,      pb);      CP16(bdst + so + 16, pb + 8);  \
        CP16(bdst + so + 32, pb + 16); CP16(bdst + so + 48, pb + 24); \
        CP16(bdst + so + 64, pb + 32); CP16(bdst + so + 80, pb + 40); \
        CP16(bdst + so + 96, pb + 48); CP16(bdst + so + 112, pb + 56);\
    } while (0)

    G2_ISSUE(0, 0); CPC();
    G2_ISSUE(1, 1); CPC();

    const int NCH = IDIM / KC;   // 64
    for (int c = 0; c < NCH; c++) {
        CPW();
        __syncthreads();
        const char* st = dsm + SM_BUF + (c % NSTG) * STG_;
        const char* Ap = st;
        const char* Bp = st + APL;
#pragma unroll
        for (int ks = 0; ks < 4; ks++) {
            uint32_t af[4][4];
#pragma unroll
            for (int mf = 0; mf < 4; mf++) {
                const char* p = Ap + (wm * 64 + mf * 16 + g) * SROWB + ks * 32 + tg * 4;
                af[mf][0] = *(const uint32_t*)p;
                af[mf][1] = *(const uint32_t*)(p + 8 * SROWB);
                af[mf][2] = *(const uint32_t*)(p + 16);
                af[mf][3] = *(const uint32_t*)(p + 8 * SROWB + 16);
            }
#pragma unroll
            for (int nf = 0; nf < 8; nf++) {
                const char* p = Bp + (wn * 64 + nf * 8 + g) * SROWB + ks * 32 + tg * 4;
                uint32_t b0 = *(const uint32_t*)p;
                uint32_t b1 = *(const uint32_t*)(p + 16);
#pragma unroll
                for (int mf = 0; mf < 4; mf++)
                    mma_h(acc[mf][nf], af[mf], b0, b1);
            }
        }
        if (c + 2 < NCH) G2_ISSUE(c + 2, (c + 2) % NSTG);
        CPC();
    }
#undef G2_ISSUE

    // epilogue: weighted store to per-slot y buffer (no atomics)
#pragma unroll
    for (int mf = 0; mf < 4; mf++) {
#pragma unroll
        for (int nf = 0; nf < 8; nf++) {
            int col = n0 + wn * 64 + nf * 8 + tg * 2;
#pragma unroll
            for (int h = 0; h < 2; h++) {
                int rl = wm * 64 + mf * 16 + g + h * 8;
                int r = m0 + rl;
                if (r < cnt) {
                    float w = sW[rl];
                    size_t o = (size_t)(off_e + r) * HDIM + col;
                    *reinterpret_cast<float2*>(g_y + o) =
                        make_float2(acc[mf][nf][2 * h] * w, acc[mf][nf][2 * h + 1] * w);
                }
            }
        }
    }
    (void)dummy;
}

// ---------------- combine: out[t] = y[slot0] + y[slot1] ----------------------
__global__ void k_combine(float* __restrict__ out) {
    const size_t n4 = (size_t)T_TOK * HDIM / 4;
    size_t i = (size_t)blockIdx.x * blockDim.x + threadIdx.x;
    for (; i < n4; i += (size_t)gridDim.x * blockDim.x) {
        int t = (int)(i / (HDIM / 4));
        int c = (int)(i % (HDIM / 4));
        int p0 = g_sl[2 * t], p1 = g_sl[2 * t + 1];
        size_t s0 = (size_t)g_off[p0 >> 13] + (p0 & 8191);
        size_t s1 = (size_t)g_off[p1 >> 13] + (p1 & 8191);
        float4 a = reinterpret_cast<const float4*>(g_y)[s0 * (HDIM / 4) + c];
        float4 b = reinterpret_cast<const float4*>(g_y)[s1 * (HDIM / 4) + c];
        reinterpret_cast<float4*>(out)[i] =
            make_float4(a.x + b.x, a.y + b.y, a.z + b.z, a.w + b.w);
    }
}

// ---------------- launch ------------------------------------------------------
extern "C" void kernel_launch(void* const* d_in, const int* in_sizes, int n_in,
                              void* d_out, int out_size) {
    const float* x      = (const float*)d_in[0];   // [T, H]
    const float* logits = (const float*)d_in[1];   // [T, E]
    const float* w13    = (const float*)d_in[2];   // [E, 2I, H]
    const float* w2     = (const float*)d_in[3];   // [E, H, I]
    float* out = (float*)d_out;                    // [T, H]
    (void)in_sizes; (void)n_in; (void)out_size;

    cudaFuncSetAttribute(k_gemm1, cudaFuncAttributeMaxDynamicSharedMemorySize, SMEM_SZ);
    cudaFuncSetAttribute(k_gemm2, cudaFuncAttributeMaxDynamicSharedMemorySize, SMEM_SZ);

    k_init<<<1, 32>>>();
    k_router<<<T_TOK / 256, 256>>>(logits);
    k_offsets<<<1, 32>>>();
    k_prep_x  <<<2048, 256>>>(x);
    k_prep_w13<<<8192, 256>>>(w13);
    k_prep_w2 <<<4096, 256>>>(w2);

    dim3 g1(T_TOK / 128, IDIM / 128, NEXP);
    k_gemm1<<<g1, 256, SMEM_SZ>>>(0);

    dim3 g2(T_TOK / 128, HDIM / 256, NEXP);
    k_gemm2<<<g2, 256, SMEM_SZ>>>(0);

    k_combine<<<2048, 256>>>(out);
}